// round 14
// baseline (speedup 1.0000x reference)
#include <cuda_runtime.h>
#include <cstdint>

// out[i] = 0.5 * sum_{bonds b with adj[b,0]==i} par[b] * (|xyz[a0]-xyz[a1]| - len[b])^2
// bond_adj arrives as int32 (JAX x64-disabled downcasts int64).
//
// L2-sector-roofline design (~28M sector-ops ≈ 71-79us floor for main kernel):
//  - xyz repacked to float4 (1 LDG.128 = 1 sector per endpoint gather)
//  - prep fully vectorized: 4 atoms/thread, float4 in/out, fused out-zeroing
//  - main kernel: 2 bonds/thread, __ldcs streaming loads (evict-first),
//    __ldg table gathers, RED.ADD scatter.

#define MAX_ATOMS 2000000
__device__ float4 g_xyz4[MAX_ATOMS];   // 32 MB static scratch

// Vectorized prep: thread t handles atoms 4t..4t+3.
// Reads 3 float4 (12 floats = 4 atoms), writes 4 float4 to table, zeroes 4 outs.
__global__ void __launch_bounds__(256)
prep_kernel_v4(const float4* __restrict__ xyz4in,  // xyz viewed as float4[3N/4]
               float4* __restrict__ out4,          // out viewed as float4[N/4]
               int nquads)                         // natoms/4
{
    int t = blockIdx.x * blockDim.x + threadIdx.x;
    if (t >= nquads) return;

    float4 v0 = __ldcs(xyz4in + 3 * t + 0);   // x0 y0 z0 x1
    float4 v1 = __ldcs(xyz4in + 3 * t + 1);   // y1 z1 x2 y2
    float4 v2 = __ldcs(xyz4in + 3 * t + 2);   // z2 x3 y3 z3

    int base = 4 * t;
    g_xyz4[base + 0] = make_float4(v0.x, v0.y, v0.z, 0.0f);
    g_xyz4[base + 1] = make_float4(v0.w, v1.x, v1.y, 0.0f);
    g_xyz4[base + 2] = make_float4(v1.z, v1.w, v2.x, 0.0f);
    g_xyz4[base + 3] = make_float4(v2.y, v2.z, v2.w, 0.0f);

    out4[t] = make_float4(0.0f, 0.0f, 0.0f, 0.0f);
}

// Scalar prep tail (natoms % 4 != 0)
__global__ void __launch_bounds__(128)
prep_kernel_tail(const float* __restrict__ xyz, float* __restrict__ out,
                 int start, int natoms)
{
    int i = start + blockIdx.x * blockDim.x + threadIdx.x;
    if (i >= natoms) return;
    out[i] = 0.0f;
    const float* p = xyz + (size_t)i * 3;
    g_xyz4[i] = make_float4(p[0], p[1], p[2], 0.0f);
}

__device__ __forceinline__ float bond_e(float4 a, float4 b, float len, float par)
{
    float dx = a.x - b.x;
    float dy = a.y - b.y;
    float dz = a.z - b.z;
    float d  = sqrtf(fmaf(dx, dx, fmaf(dy, dy, dz * dz)));
    float t  = d - len;
    return 0.5f * par * t * t;
}

// 2 bonds per thread; streams evict-first, gathers via read-only path
__global__ void __launch_bounds__(256, 8)
bond_energy_kernel(const int4*   __restrict__ adj2,  // [E/2]: two pairs per int4
                   const float2* __restrict__ blen2, // [E/2]
                   const float2* __restrict__ bpar2, // [E/2]
                   float* __restrict__ out,          // [N]
                   int npairs)                       // E/2
{
    int p = blockIdx.x * blockDim.x + threadIdx.x;
    if (p >= npairs) return;

    int4   ij  = __ldcs(adj2 + p);    // (i0,j0,i1,j1) — read-once stream
    float2 len = __ldcs(blen2 + p);
    float2 par = __ldcs(bpar2 + p);

    // 4 independent gathers in flight before any FP work
    float4 a0 = __ldg(&g_xyz4[ij.x]);
    float4 b0 = __ldg(&g_xyz4[ij.y]);
    float4 a1 = __ldg(&g_xyz4[ij.z]);
    float4 b1 = __ldg(&g_xyz4[ij.w]);

    atomicAdd(out + ij.x, bond_e(a0, b0, len.x, par.x));
    atomicAdd(out + ij.z, bond_e(a1, b1, len.y, par.y));
}

// Tail for odd bond counts
__global__ void __launch_bounds__(128)
bond_energy_tail_kernel(const int2*  __restrict__ adj,
                        const float* __restrict__ blen,
                        const float* __restrict__ bpar,
                        float* __restrict__ out,
                        int start, int nbonds)
{
    int e = start + blockIdx.x * blockDim.x + threadIdx.x;
    if (e >= nbonds) return;
    int2 ij = __ldg(adj + e);
    float4 a = __ldg(&g_xyz4[ij.x]);
    float4 b = __ldg(&g_xyz4[ij.y]);
    atomicAdd(out + ij.x, bond_e(a, b, __ldg(blen + e), __ldg(bpar + e)));
}

extern "C" void kernel_launch(void* const* d_in, const int* in_sizes, int n_in,
                              void* d_out, int out_size)
{
    const float* xyz  = (const float*)d_in[0];  // [N,3]
    const int2*  adj  = (const int2*)d_in[1];   // [E,2] int32
    const float* blen = (const float*)d_in[2];  // [E,1]
    const float* bpar = (const float*)d_in[3];  // [E,1]
    float*       out  = (float*)d_out;          // [N,1]

    int nbonds = in_sizes[1] / 2;
    int natoms = out_size;

    // ---- prep: zero out + repack xyz to float4 table ----
    int aquads = natoms / 4;
    int atail  = aquads * 4;
    if (aquads > 0) {
        int threads = 256;
        prep_kernel_v4<<<(aquads + threads - 1) / threads, threads>>>(
            (const float4*)xyz, (float4*)out, aquads);
    }
    if (atail < natoms) {
        int threads = 128;
        int n = natoms - atail;
        prep_kernel_tail<<<(n + threads - 1) / threads, threads>>>(
            xyz, out, atail, natoms);
    }

    // ---- main: bond energies + scatter ----
    int npairs = nbonds / 2;
    int btail  = npairs * 2;
    if (npairs > 0) {
        int threads = 256;
        bond_energy_kernel<<<(npairs + threads - 1) / threads, threads>>>(
            (const int4*)adj, (const float2*)blen, (const float2*)bpar, out, npairs);
    }
    if (btail < nbonds) {
        int threads = 128;
        int n = nbonds - btail;
        bond_energy_tail_kernel<<<(n + threads - 1) / threads, threads>>>(
            adj, blen, bpar, out, btail, nbonds);
    }
}

// round 16
// speedup vs baseline: 1.0333x; 1.0333x over previous
#include <cuda_runtime.h>
#include <cstdint>

// out[i] = 0.5 * sum_{bonds b with adj[b,0]==i} par[b] * (|xyz[a0]-xyz[a1]| - len[b])^2
// bond_adj arrives as int32 (JAX x64-disabled downcasts int64).
//
// Floor model (measured): main kernel ~3.1 L1tex wavefronts/bond
// (2 float4 gathers + 1 atomic + streams) -> ~90us; prep ~8us DRAM-bound.
//  - xyz repacked to float4 table (1 LDG.128 = 1 sector per endpoint gather)
//  - prep: smem-transpose, fully coalesced loads AND stores, fused out-zeroing
//  - main: 2 bonds/thread (int4 adj), plain __ldg everywhere (ldcs was neutral)

#define MAX_ATOMS 2000000
__device__ float4 g_xyz4[MAX_ATOMS];   // 32 MB static scratch

// Prep: block handles 256 atoms. 768 coalesced 4B loads -> smem ->
// conflict-free stride-3 reads -> coalesced 16B table stores. Zero out[].
__global__ void __launch_bounds__(256)
prep_kernel(const float* __restrict__ xyz, float* __restrict__ out, int natoms)
{
    __shared__ float s[768];
    int base = blockIdx.x * 256;
    int remaining = natoms - base;
    if (remaining <= 0) return;
    int natoms_blk = remaining < 256 ? remaining : 256;
    int nfloats = 3 * natoms_blk;

    const float* src = xyz + (size_t)base * 3;
    for (int k = threadIdx.x; k < nfloats; k += 256)
        s[k] = __ldg(src + k);
    __syncthreads();

    int tid = threadIdx.x;
    if (tid < natoms_blk) {
        // stride-3 smem read: 3 coprime with 32 banks -> conflict-free
        g_xyz4[base + tid] = make_float4(s[3 * tid], s[3 * tid + 1], s[3 * tid + 2], 0.0f);
        out[base + tid] = 0.0f;
    }
}

__device__ __forceinline__ float bond_e(float4 a, float4 b, float len, float par)
{
    float dx = a.x - b.x;
    float dy = a.y - b.y;
    float dz = a.z - b.z;
    float d  = sqrtf(fmaf(dx, dx, fmaf(dy, dy, dz * dz)));
    float t  = d - len;
    return 0.5f * par * t * t;
}

// 2 bonds per thread (best measured config: R11, main 91.7us)
__global__ void __launch_bounds__(256, 8)
bond_energy_kernel(const int4*   __restrict__ adj2,  // [E/2]: two pairs per int4
                   const float2* __restrict__ blen2, // [E/2]
                   const float2* __restrict__ bpar2, // [E/2]
                   float* __restrict__ out,          // [N]
                   int npairs)                       // E/2
{
    int p = blockIdx.x * blockDim.x + threadIdx.x;
    if (p >= npairs) return;

    int4   ij  = __ldg(adj2 + p);    // (i0,j0,i1,j1)
    float2 len = __ldg(blen2 + p);
    float2 par = __ldg(bpar2 + p);

    // 4 independent gathers in flight before any FP work
    float4 a0 = __ldg(&g_xyz4[ij.x]);
    float4 b0 = __ldg(&g_xyz4[ij.y]);
    float4 a1 = __ldg(&g_xyz4[ij.z]);
    float4 b1 = __ldg(&g_xyz4[ij.w]);

    atomicAdd(out + ij.x, bond_e(a0, b0, len.x, par.x));
    atomicAdd(out + ij.z, bond_e(a1, b1, len.y, par.y));
}

// Tail for odd bond counts
__global__ void __launch_bounds__(128)
bond_energy_tail_kernel(const int2*  __restrict__ adj,
                        const float* __restrict__ blen,
                        const float* __restrict__ bpar,
                        float* __restrict__ out,
                        int start, int nbonds)
{
    int e = start + blockIdx.x * blockDim.x + threadIdx.x;
    if (e >= nbonds) return;
    int2 ij = __ldg(adj + e);
    float4 a = __ldg(&g_xyz4[ij.x]);
    float4 b = __ldg(&g_xyz4[ij.y]);
    atomicAdd(out + ij.x, bond_e(a, b, __ldg(blen + e), __ldg(bpar + e)));
}

extern "C" void kernel_launch(void* const* d_in, const int* in_sizes, int n_in,
                              void* d_out, int out_size)
{
    const float* xyz  = (const float*)d_in[0];  // [N,3]
    const int2*  adj  = (const int2*)d_in[1];   // [E,2] int32
    const float* blen = (const float*)d_in[2];  // [E,1]
    const float* bpar = (const float*)d_in[3];  // [E,1]
    float*       out  = (float*)d_out;          // [N,1]

    int nbonds = in_sizes[1] / 2;
    int natoms = out_size;

    // ---- prep: zero out + repack xyz to float4 table (one launch) ----
    {
        int blocks = (natoms + 255) / 256;
        prep_kernel<<<blocks, 256>>>(xyz, out, natoms);
    }

    // ---- main: bond energies + scatter ----
    int npairs = nbonds / 2;
    int btail  = npairs * 2;
    if (npairs > 0) {
        int threads = 256;
        bond_energy_kernel<<<(npairs + threads - 1) / threads, threads>>>(
            (const int4*)adj, (const float2*)blen, (const float2*)bpar, out, npairs);
    }
    if (btail < nbonds) {
        int threads = 128;
        int n = nbonds - btail;
        bond_energy_tail_kernel<<<(n + threads - 1) / threads, threads>>>(
            adj, blen, bpar, out, btail, nbonds);
    }
}